// round 1
// baseline (speedup 1.0000x reference)
#include <cuda_runtime.h>
#include <cstdint>

// Problem constants
#define B_    4
#define T_    2048
#define C_DIM 1024
#define H_    16
#define D_    64
#define M_ROWS (B_*T_)      // 8192
#define QKV_N  (3*C_DIM)    // 3072
#define NEG_BIG (-3.0e38f)

// Scratch (device globals: the allowed allocation-free scratch mechanism)
__device__ float g_q[8388608];   // [B,H,T,D]
__device__ float g_k[8388608];
__device__ float g_v[8388608];
__device__ float g_y[8388608];   // [B,T,C]

// ---------------------------------------------------------------------------
// GEMM: out[m,n] = sum_k A[m,k]*W[n,k] + bias[n]   (both operands K-major)
// Tile 128x128x16, 256 threads, 8x8 per-thread micro-tile.
// MODE 0: plain store to out[m*N+n]. MODE 1: scatter into g_q/g_k/g_v [B,H,T,D].
// ---------------------------------------------------------------------------
template<int MODE>
__global__ void __launch_bounds__(256) gemm_tn_kernel(
    const float* __restrict__ A, const float* __restrict__ W,
    const float* __restrict__ bias, float* __restrict__ out,
    int N, int K)
{
    __shared__ float Ast[16][128];
    __shared__ float Bst[16][128];

    const int tid = threadIdx.x;
    const int tx = tid & 15;      // output column group
    const int ty = tid >> 4;      // output row group
    const int rowBase = blockIdx.y * 128;
    const int colBase = blockIdx.x * 128;

    float acc[8][8];
    #pragma unroll
    for (int i = 0; i < 8; ++i)
        #pragma unroll
        for (int j = 0; j < 8; ++j) acc[i][j] = 0.f;

    const int lr = tid >> 1;            // tile row this thread loads
    const int lk = (tid & 1) << 3;      // k offset 0 or 8
    const float* Ap = A + (size_t)(rowBase + lr) * K + lk;
    const float* Wp = W + (size_t)(colBase + lr) * K + lk;

    for (int k0 = 0; k0 < K; k0 += 16) {
        #pragma unroll
        for (int t = 0; t < 2; ++t) {
            const int kq = lk + t * 4;
            float4 va = *(const float4*)(Ap + k0 + t * 4);
            Ast[kq+0][lr] = va.x; Ast[kq+1][lr] = va.y;
            Ast[kq+2][lr] = va.z; Ast[kq+3][lr] = va.w;
            float4 vb = *(const float4*)(Wp + k0 + t * 4);
            Bst[kq+0][lr] = vb.x; Bst[kq+1][lr] = vb.y;
            Bst[kq+2][lr] = vb.z; Bst[kq+3][lr] = vb.w;
        }
        __syncthreads();
        #pragma unroll
        for (int kk = 0; kk < 16; ++kk) {
            float a[8], b[8];
            *(float4*)&a[0] = *(const float4*)&Ast[kk][ty*8];
            *(float4*)&a[4] = *(const float4*)&Ast[kk][ty*8 + 4];
            *(float4*)&b[0] = *(const float4*)&Bst[kk][tx*8];
            *(float4*)&b[4] = *(const float4*)&Bst[kk][tx*8 + 4];
            #pragma unroll
            for (int i = 0; i < 8; ++i)
                #pragma unroll
                for (int j = 0; j < 8; ++j)
                    acc[i][j] += a[i] * b[j];
        }
        __syncthreads();
    }

    // Epilogue (vectorized float4 stores)
    #pragma unroll
    for (int i = 0; i < 8; ++i) {
        const int m = rowBase + ty*8 + i;
        #pragma unroll
        for (int jj = 0; jj < 2; ++jj) {
            const int n0 = colBase + tx*8 + jj*4;
            float4 v;
            v.x = acc[i][jj*4+0] + bias[n0+0];
            v.y = acc[i][jj*4+1] + bias[n0+1];
            v.z = acc[i][jj*4+2] + bias[n0+2];
            v.w = acc[i][jj*4+3] + bias[n0+3];
            if (MODE == 0) {
                *(float4*)(out + (size_t)m * N + n0) = v;
            } else {
                const int sector = n0 >> 10;          // 0=Q 1=K 2=V
                const int c  = n0 & 1023;
                const int hh = c >> 6, dd = c & 63;
                const int bb = m >> 11, tt = m & 2047;
                float* dst = (sector == 0) ? g_q : (sector == 1) ? g_k : g_v;
                *(float4*)(dst + ((((size_t)bb * H_ + hh) * T_) + tt) * D_ + dd) = v;
            }
        }
    }
}

// ---------------------------------------------------------------------------
// Flash attention, fp32. One CTA = (b,h, 64-query tile), 256 threads.
// Shared (dynamic, 70144 B): Qt[d][q] (pre-scaled), Kt[d][k], Vs[k][d],
// Ss[q][k] (P values), alf[64], larr[64]. PITCH=68 for conflict avoidance.
// S-phase mapping : warp w owns q-rows w*8..w*8+7, lane owns k-cols lane*2,+1.
// PV-phase mapping: thread (ty,tx) owns q-rows ty*4..+3, d-cols tx*4..+3.
// ---------------------------------------------------------------------------
#define PITCH 68
#define ATTN_SMEM ((4*64*PITCH + 128) * (int)sizeof(float))

__global__ void __launch_bounds__(256) attn_kernel(float* __restrict__ Y)
{
    extern __shared__ float sm[];
    float* Qt   = sm;
    float* Kt   = Qt + 64*PITCH;
    float* Vs   = Kt + 64*PITCH;
    float* Ss   = Vs + 64*PITCH;
    float* alf  = Ss + 64*PITCH;
    float* larr = alf + 64;

    const int qt  = gridDim.x - 1 - blockIdx.x;   // big tiles first
    const int bh  = blockIdx.y;
    const int b   = bh >> 4, h = bh & 15;
    const int tid = threadIdx.x;
    const int lane = tid & 31, w = tid >> 5;
    const int tx = tid & 15, ty = tid >> 4;
    const float scale = 0.125f;                   // 1/sqrt(64)

    const float* Qg = g_q + ((size_t)bh * T_ + qt * 64) * D_;
    const float* Kg = g_k + (size_t)bh * T_ * D_;
    const float* Vg = g_v + (size_t)bh * T_ * D_;

    // Load Q tile transposed ([d][q]) with scale folded in
    #pragma unroll
    for (int t2 = 0; t2 < 4; ++t2) {
        const int slot = tid + t2 * 256;          // 0..1023
        const int r  = slot >> 4;
        const int d0 = (slot & 15) << 2;
        float4 vq = *(const float4*)(Qg + r * 64 + d0);
        Qt[(d0+0)*PITCH + r] = vq.x * scale;
        Qt[(d0+1)*PITCH + r] = vq.y * scale;
        Qt[(d0+2)*PITCH + r] = vq.z * scale;
        Qt[(d0+3)*PITCH + r] = vq.w * scale;
    }

    float mreg[8], lreg[8];
    #pragma unroll
    for (int i = 0; i < 8; ++i) { mreg[i] = NEG_BIG; lreg[i] = 0.f; }
    float acc[4][4];
    #pragma unroll
    for (int i = 0; i < 4; ++i)
        #pragma unroll
        for (int j = 0; j < 4; ++j) acc[i][j] = 0.f;

    for (int kt = 0; kt <= qt; ++kt) {
        const float* Kgt = Kg + kt * 64 * 64;
        const float* Vgt = Vg + kt * 64 * 64;
        #pragma unroll
        for (int t2 = 0; t2 < 4; ++t2) {
            const int slot = tid + t2 * 256;
            const int r  = slot >> 4;
            const int d0 = (slot & 15) << 2;
            float4 vk = *(const float4*)(Kgt + r * 64 + d0);
            Kt[(d0+0)*PITCH + r] = vk.x;
            Kt[(d0+1)*PITCH + r] = vk.y;
            Kt[(d0+2)*PITCH + r] = vk.z;
            Kt[(d0+3)*PITCH + r] = vk.w;
            float4 vv = *(const float4*)(Vgt + r * 64 + d0);
            *(float4*)(Vs + r * PITCH + d0) = vv;
        }
        __syncthreads();

        // ---- S = Q K^T (scaled) ----
        float s[8][2];
        #pragma unroll
        for (int i = 0; i < 8; ++i) { s[i][0] = 0.f; s[i][1] = 0.f; }
        #pragma unroll 4
        for (int d = 0; d < 64; ++d) {
            float4 a0 = *(const float4*)(Qt + d*PITCH + w*8);
            float4 a1 = *(const float4*)(Qt + d*PITCH + w*8 + 4);
            float2 kb = *(const float2*)(Kt + d*PITCH + lane*2);
            s[0][0] += a0.x*kb.x; s[0][1] += a0.x*kb.y;
            s[1][0] += a0.y*kb.x; s[1][1] += a0.y*kb.y;
            s[2][0] += a0.z*kb.x; s[2][1] += a0.z*kb.y;
            s[3][0] += a0.w*kb.x; s[3][1] += a0.w*kb.y;
            s[4][0] += a1.x*kb.x; s[4][1] += a1.x*kb.y;
            s[5][0] += a1.y*kb.x; s[5][1] += a1.y*kb.y;
            s[6][0] += a1.z*kb.x; s[6][1] += a1.z*kb.y;
            s[7][0] += a1.w*kb.x; s[7][1] += a1.w*kb.y;
        }

        // Causal mask (only the diagonal tile needs it)
        if (kt == qt) {
            #pragma unroll
            for (int i = 0; i < 8; ++i) {
                const int qr = w*8 + i;
                if (lane*2     > qr) s[i][0] = NEG_BIG;
                if (lane*2 + 1 > qr) s[i][1] = NEG_BIG;
            }
        }

        // ---- online softmax (per-row warp reductions) ----
        #pragma unroll
        for (int i = 0; i < 8; ++i) {
            float rmax = fmaxf(s[i][0], s[i][1]);
            #pragma unroll
            for (int off = 16; off; off >>= 1)
                rmax = fmaxf(rmax, __shfl_xor_sync(0xffffffffu, rmax, off));
            const float mnew = fmaxf(mreg[i], rmax);
            const float p0 = __expf(s[i][0] - mnew);
            const float p1 = __expf(s[i][1] - mnew);
            float rsum = p0 + p1;
            #pragma unroll
            for (int off = 16; off; off >>= 1)
                rsum += __shfl_xor_sync(0xffffffffu, rsum, off);
            const float al = __expf(mreg[i] - mnew);
            lreg[i] = lreg[i] * al + rsum;
            mreg[i] = mnew;
            *(float2*)(Ss + (w*8 + i)*PITCH + lane*2) = make_float2(p0, p1);
            if (lane == 0) alf[w*8 + i] = al;
        }
        __syncthreads();

        // ---- O = O*alpha + P V ----
        float alv[4];
        #pragma unroll
        for (int i = 0; i < 4; ++i) alv[i] = alf[ty*4 + i];
        #pragma unroll
        for (int i = 0; i < 4; ++i)
            #pragma unroll
            for (int j = 0; j < 4; ++j) acc[i][j] *= alv[i];

        #pragma unroll 4
        for (int kx = 0; kx < 64; ++kx) {
            float4 bv = *(const float4*)(Vs + kx*PITCH + tx*4);
            float a0 = Ss[(ty*4+0)*PITCH + kx];
            float a1 = Ss[(ty*4+1)*PITCH + kx];
            float a2 = Ss[(ty*4+2)*PITCH + kx];
            float a3 = Ss[(ty*4+3)*PITCH + kx];
            acc[0][0] += a0*bv.x; acc[0][1] += a0*bv.y; acc[0][2] += a0*bv.z; acc[0][3] += a0*bv.w;
            acc[1][0] += a1*bv.x; acc[1][1] += a1*bv.y; acc[1][2] += a1*bv.z; acc[1][3] += a1*bv.w;
            acc[2][0] += a2*bv.x; acc[2][1] += a2*bv.y; acc[2][2] += a2*bv.z; acc[2][3] += a2*bv.w;
            acc[3][0] += a3*bv.x; acc[3][1] += a3*bv.y; acc[3][2] += a3*bv.z; acc[3][3] += a3*bv.w;
        }
        __syncthreads();
    }

    // Epilogue: normalize and write y in [B,T,C] with head offset
    if (lane == 0) {
        #pragma unroll
        for (int i = 0; i < 8; ++i) larr[w*8 + i] = lreg[i];
    }
    __syncthreads();
    #pragma unroll
    for (int i = 0; i < 4; ++i) {
        const float inv = 1.0f / larr[ty*4 + i];
        const int gq = qt*64 + ty*4 + i;
        float4 o;
        o.x = acc[i][0]*inv; o.y = acc[i][1]*inv;
        o.z = acc[i][2]*inv; o.w = acc[i][3]*inv;
        *(float4*)(Y + ((size_t)b * T_ + gq) * C_DIM + h*64 + tx*4) = o;
    }
}

// ---------------------------------------------------------------------------
extern "C" void kernel_launch(void* const* d_in, const int* in_sizes, int n_in,
                              void* d_out, int out_size)
{
    const float* x      = (const float*)d_in[0];
    const float* w_attn = (const float*)d_in[1];
    const float* b_attn = (const float*)d_in[2];
    const float* w_proj = (const float*)d_in[3];
    const float* b_proj = (const float*)d_in[4];
    float* out = (float*)d_out;

    float* yptr = nullptr;
    cudaGetSymbolAddress((void**)&yptr, g_y);

    cudaFuncSetAttribute(attn_kernel,
                         cudaFuncAttributeMaxDynamicSharedMemorySize, ATTN_SMEM);

    // 1) QKV projection, epilogue scatters to head-major Q/K/V
    dim3 g1(QKV_N / 128, M_ROWS / 128);   // 24 x 64
    gemm_tn_kernel<1><<<g1, 256>>>(x, w_attn, b_attn, nullptr, QKV_N, C_DIM);

    // 2) Causal flash attention -> g_y [B,T,C]
    dim3 g2(T_ / 64, B_ * H_);            // 32 x 64
    attn_kernel<<<g2, 256, ATTN_SMEM>>>(yptr);

    // 3) Output projection -> d_out
    dim3 g3(C_DIM / 128, M_ROWS / 128);   // 8 x 64
    gemm_tn_kernel<0><<<g3, 256>>>(yptr, w_proj, b_proj, out, C_DIM, C_DIM);
}

// round 3
// speedup vs baseline: 1.5281x; 1.5281x over previous
#include <cuda_runtime.h>
#include <cstdint>

// Problem constants
#define B_    4
#define T_    2048
#define C_DIM 1024
#define H_    16
#define D_    64
#define M_ROWS (B_*T_)      // 8192
#define QKV_N  (3*C_DIM)    // 3072
#define NEG_BIG (-3.0e38f)

// Scratch (device globals)
__device__ float g_q[8388608];   // [B,H,T,D]
__device__ float g_k[8388608];
__device__ float g_v[8388608];
__device__ float g_y[8388608];   // [B,T,C]

// ---------------------------------------------------------------------------
// tf32 mma.sync GEMM: out[m,n] = sum_k A[m,k]*W[n,k] + bias[n]
// Block tile 128x128x32, 256 threads (8 warps, 2x4), warp tile 64x32.
// smem pad 36 floats/row -> conflict-free fragment LDS (bank = 4*(lane>>2)+(lane&3)).
// cp.async double buffer. RNE tf32 rounding at fragment load.
// MODE 0: plain store. MODE 1: scatter into g_q/g_k/g_v [B,H,T,D].
// ---------------------------------------------------------------------------
#define GPAD 36
#define GSM_BUF (128*GPAD)                 // floats per matrix per stage
#define GEMM_SMEM (4*GSM_BUF*(int)sizeof(float))  // 73728 B

__device__ __forceinline__ uint32_t cvta_smem(const void* p) {
    uint32_t a;
    asm("{ .reg .u64 t; cvta.to.shared.u64 t, %1; cvt.u32.u64 %0, t; }"
        : "=r"(a) : "l"(p));
    return a;
}
__device__ __forceinline__ void cp_async16(uint32_t dst, const void* src) {
    asm volatile("cp.async.cg.shared.global [%0], [%1], 16;" :: "r"(dst), "l"(src));
}
__device__ __forceinline__ void cp_commit() { asm volatile("cp.async.commit_group;"); }
__device__ __forceinline__ void cp_wait1()  { asm volatile("cp.async.wait_group 1;"); }
__device__ __forceinline__ void cp_wait0()  { asm volatile("cp.async.wait_group 0;"); }

// tf32 RNE rounding: destination of cvt.*.tf32 must be a .b32 register.
__device__ __forceinline__ uint32_t tf32_rne(float x) {
    uint32_t y;
    asm("cvt.rna.tf32.f32 %0, %1;" : "=r"(y) : "f"(x));
    return y;
}
__device__ __forceinline__ void mma_tf32(float* d, const uint32_t* a, const uint32_t* b) {
    asm volatile(
        "mma.sync.aligned.m16n8k8.row.col.f32.tf32.tf32.f32 "
        "{%0,%1,%2,%3}, {%4,%5,%6,%7}, {%8,%9}, {%0,%1,%2,%3};"
        : "+f"(d[0]), "+f"(d[1]), "+f"(d[2]), "+f"(d[3])
        : "r"(a[0]), "r"(a[1]), "r"(a[2]), "r"(a[3]), "r"(b[0]), "r"(b[1]));
}

template<int MODE>
__global__ void __launch_bounds__(256) gemm_mma_kernel(
    const float* __restrict__ A, const float* __restrict__ W,
    const float* __restrict__ bias, float* __restrict__ out,
    int N, int K)
{
    extern __shared__ float sm[];
    const int tid  = threadIdx.x;
    const int lane = tid & 31;
    const int wid  = tid >> 5;
    const int wm   = wid & 1;        // warp row (0..1) -> 64 rows each
    const int wn   = wid >> 1;       // warp col (0..3) -> 32 cols each
    const int qr   = lane >> 2;      // 0..7
    const int qc   = lane & 3;       // 0..3

    const int rowBase = blockIdx.y * 128;
    const int colBase = blockIdx.x * 128;

    // Loader mapping: row = tid>>1 (0..127), k0 = (tid&1)*16, 4 x 16B each for A and B
    const int lrow = tid >> 1;
    const int lk0  = (tid & 1) << 4;
    const float* Asrc = A + (size_t)(rowBase + lrow) * K + lk0;
    const float* Wsrc = W + (size_t)(colBase + lrow) * K + lk0;
    const uint32_t smem_base = cvta_smem(sm);
    const uint32_t dstA = smem_base + (lrow * GPAD + lk0) * 4;
    const uint32_t dstB = dstA + GSM_BUF * 4;

    float acc[4][4][4];
    #pragma unroll
    for (int i = 0; i < 4; ++i)
        #pragma unroll
        for (int j = 0; j < 4; ++j)
            #pragma unroll
            for (int r = 0; r < 4; ++r) acc[i][j][r] = 0.f;

    const int nk = K >> 5;   // 32-wide k tiles

    // Prologue: issue tile 0 into stage 0
    #pragma unroll
    for (int j = 0; j < 4; ++j) {
        cp_async16(dstA + j * 16, Asrc + j * 4);
        cp_async16(dstB + j * 16, Wsrc + j * 4);
    }
    cp_commit();

    for (int kt = 0; kt < nk; ++kt) {
        // Issue next tile into the other stage, then wait for current
        if (kt + 1 < nk) {
            const uint32_t stoff = ((kt + 1) & 1) ? (uint32_t)(2 * GSM_BUF * 4) : 0u;
            const float* An = Asrc + (size_t)(kt + 1) * 32;
            const float* Wn = Wsrc + (size_t)(kt + 1) * 32;
            #pragma unroll
            for (int j = 0; j < 4; ++j) {
                cp_async16(dstA + stoff + j * 16, An + j * 4);
                cp_async16(dstB + stoff + j * 16, Wn + j * 4);
            }
            cp_commit();
            cp_wait1();
        } else {
            cp_wait0();
        }
        __syncthreads();

        const float* As = sm + ((kt & 1) ? 2 * GSM_BUF : 0);
        const float* Bs = As + GSM_BUF;

        #pragma unroll
        for (int ks = 0; ks < 4; ++ks) {
            const int kk = ks * 8 + qc;
            uint32_t af[4][4], bf[4][2];
            #pragma unroll
            for (int mt = 0; mt < 4; ++mt) {
                const int r = wm * 64 + mt * 16 + qr;
                af[mt][0] = tf32_rne(As[r * GPAD + kk]);
                af[mt][1] = tf32_rne(As[(r + 8) * GPAD + kk]);
                af[mt][2] = tf32_rne(As[r * GPAD + kk + 4]);
                af[mt][3] = tf32_rne(As[(r + 8) * GPAD + kk + 4]);
            }
            #pragma unroll
            for (int nt = 0; nt < 4; ++nt) {
                const int c = wn * 32 + nt * 8 + qr;
                bf[nt][0] = tf32_rne(Bs[c * GPAD + kk]);
                bf[nt][1] = tf32_rne(Bs[c * GPAD + kk + 4]);
            }
            #pragma unroll
            for (int mt = 0; mt < 4; ++mt)
                #pragma unroll
                for (int nt = 0; nt < 4; ++nt)
                    mma_tf32(acc[mt][nt], af[mt], bf[nt]);
        }
        __syncthreads();
    }

    // Epilogue: c0,c1 at (row qr, cols qc*2, qc*2+1); c2,c3 at row qr+8
    #pragma unroll
    for (int nt = 0; nt < 4; ++nt) {
        const int n0 = colBase + wn * 32 + nt * 8 + qc * 2;
        const float b0 = bias[n0], b1 = bias[n0 + 1];
        #pragma unroll
        for (int mt = 0; mt < 4; ++mt) {
            const int m0 = rowBase + wm * 64 + mt * 16 + qr;
            float2 v0 = make_float2(acc[mt][nt][0] + b0, acc[mt][nt][1] + b1);
            float2 v1 = make_float2(acc[mt][nt][2] + b0, acc[mt][nt][3] + b1);
            if (MODE == 0) {
                *(float2*)(out + (size_t)m0 * N + n0)       = v0;
                *(float2*)(out + (size_t)(m0 + 8) * N + n0) = v1;
            } else {
                const int sector = n0 >> 10;          // 0=Q 1=K 2=V
                const int c  = n0 & 1023;
                const int hh = c >> 6, dd = c & 63;
                float* dst = (sector == 0) ? g_q : (sector == 1) ? g_k : g_v;
                const int bb0 = m0 >> 11, tt0 = m0 & 2047;
                *(float2*)(dst + ((((size_t)bb0 * H_ + hh) * T_) + tt0) * D_ + dd) = v0;
                const int m1 = m0 + 8;
                const int bb1 = m1 >> 11, tt1 = m1 & 2047;
                *(float2*)(dst + ((((size_t)bb1 * H_ + hh) * T_) + tt1) * D_ + dd) = v1;
            }
        }
    }
}

// ---------------------------------------------------------------------------
// Flash attention, fp32 (unchanged from round 1).
// ---------------------------------------------------------------------------
#define PITCH 68
#define ATTN_SMEM ((4*64*PITCH + 128) * (int)sizeof(float))

__global__ void __launch_bounds__(256) attn_kernel(float* __restrict__ Y)
{
    extern __shared__ float sm[];
    float* Qt   = sm;
    float* Kt   = Qt + 64*PITCH;
    float* Vs   = Kt + 64*PITCH;
    float* Ss   = Vs + 64*PITCH;
    float* alf  = Ss + 64*PITCH;
    float* larr = alf + 64;

    const int qt  = gridDim.x - 1 - blockIdx.x;
    const int bh  = blockIdx.y;
    const int b   = bh >> 4, h = bh & 15;
    const int tid = threadIdx.x;
    const int lane = tid & 31, w = tid >> 5;
    const int tx = tid & 15, ty = tid >> 4;
    const float scale = 0.125f;

    const float* Qg = g_q + ((size_t)bh * T_ + qt * 64) * D_;
    const float* Kg = g_k + (size_t)bh * T_ * D_;
    const float* Vg = g_v + (size_t)bh * T_ * D_;

    #pragma unroll
    for (int t2 = 0; t2 < 4; ++t2) {
        const int slot = tid + t2 * 256;
        const int r  = slot >> 4;
        const int d0 = (slot & 15) << 2;
        float4 vq = *(const float4*)(Qg + r * 64 + d0);
        Qt[(d0+0)*PITCH + r] = vq.x * scale;
        Qt[(d0+1)*PITCH + r] = vq.y * scale;
        Qt[(d0+2)*PITCH + r] = vq.z * scale;
        Qt[(d0+3)*PITCH + r] = vq.w * scale;
    }

    float mreg[8], lreg[8];
    #pragma unroll
    for (int i = 0; i < 8; ++i) { mreg[i] = NEG_BIG; lreg[i] = 0.f; }
    float acc[4][4];
    #pragma unroll
    for (int i = 0; i < 4; ++i)
        #pragma unroll
        for (int j = 0; j < 4; ++j) acc[i][j] = 0.f;

    for (int kt = 0; kt <= qt; ++kt) {
        const float* Kgt = Kg + kt * 64 * 64;
        const float* Vgt = Vg + kt * 64 * 64;
        #pragma unroll
        for (int t2 = 0; t2 < 4; ++t2) {
            const int slot = tid + t2 * 256;
            const int r  = slot >> 4;
            const int d0 = (slot & 15) << 2;
            float4 vk = *(const float4*)(Kgt + r * 64 + d0);
            Kt[(d0+0)*PITCH + r] = vk.x;
            Kt[(d0+1)*PITCH + r] = vk.y;
            Kt[(d0+2)*PITCH + r] = vk.z;
            Kt[(d0+3)*PITCH + r] = vk.w;
            float4 vv = *(const float4*)(Vgt + r * 64 + d0);
            *(float4*)(Vs + r * PITCH + d0) = vv;
        }
        __syncthreads();

        float s[8][2];
        #pragma unroll
        for (int i = 0; i < 8; ++i) { s[i][0] = 0.f; s[i][1] = 0.f; }
        #pragma unroll 4
        for (int d = 0; d < 64; ++d) {
            float4 a0 = *(const float4*)(Qt + d*PITCH + w*8);
            float4 a1 = *(const float4*)(Qt + d*PITCH + w*8 + 4);
            float2 kb = *(const float2*)(Kt + d*PITCH + lane*2);
            s[0][0] += a0.x*kb.x; s[0][1] += a0.x*kb.y;
            s[1][0] += a0.y*kb.x; s[1][1] += a0.y*kb.y;
            s[2][0] += a0.z*kb.x; s[2][1] += a0.z*kb.y;
            s[3][0] += a0.w*kb.x; s[3][1] += a0.w*kb.y;
            s[4][0] += a1.x*kb.x; s[4][1] += a1.x*kb.y;
            s[5][0] += a1.y*kb.x; s[5][1] += a1.y*kb.y;
            s[6][0] += a1.z*kb.x; s[6][1] += a1.z*kb.y;
            s[7][0] += a1.w*kb.x; s[7][1] += a1.w*kb.y;
        }

        if (kt == qt) {
            #pragma unroll
            for (int i = 0; i < 8; ++i) {
                const int qrr = w*8 + i;
                if (lane*2     > qrr) s[i][0] = NEG_BIG;
                if (lane*2 + 1 > qrr) s[i][1] = NEG_BIG;
            }
        }

        #pragma unroll
        for (int i = 0; i < 8; ++i) {
            float rmax = fmaxf(s[i][0], s[i][1]);
            #pragma unroll
            for (int off = 16; off; off >>= 1)
                rmax = fmaxf(rmax, __shfl_xor_sync(0xffffffffu, rmax, off));
            const float mnew = fmaxf(mreg[i], rmax);
            const float p0 = __expf(s[i][0] - mnew);
            const float p1 = __expf(s[i][1] - mnew);
            float rsum = p0 + p1;
            #pragma unroll
            for (int off = 16; off; off >>= 1)
                rsum += __shfl_xor_sync(0xffffffffu, rsum, off);
            const float al = __expf(mreg[i] - mnew);
            lreg[i] = lreg[i] * al + rsum;
            mreg[i] = mnew;
            *(float2*)(Ss + (w*8 + i)*PITCH + lane*2) = make_float2(p0, p1);
            if (lane == 0) alf[w*8 + i] = al;
        }
        __syncthreads();

        float alv[4];
        #pragma unroll
        for (int i = 0; i < 4; ++i) alv[i] = alf[ty*4 + i];
        #pragma unroll
        for (int i = 0; i < 4; ++i)
            #pragma unroll
            for (int j = 0; j < 4; ++j) acc[i][j] *= alv[i];

        #pragma unroll 4
        for (int kx = 0; kx < 64; ++kx) {
            float4 bv = *(const float4*)(Vs + kx*PITCH + tx*4);
            float a0 = Ss[(ty*4+0)*PITCH + kx];
            float a1 = Ss[(ty*4+1)*PITCH + kx];
            float a2 = Ss[(ty*4+2)*PITCH + kx];
            float a3 = Ss[(ty*4+3)*PITCH + kx];
            acc[0][0] += a0*bv.x; acc[0][1] += a0*bv.y; acc[0][2] += a0*bv.z; acc[0][3] += a0*bv.w;
            acc[1][0] += a1*bv.x; acc[1][1] += a1*bv.y; acc[1][2] += a1*bv.z; acc[1][3] += a1*bv.w;
            acc[2][0] += a2*bv.x; acc[2][1] += a2*bv.y; acc[2][2] += a2*bv.z; acc[2][3] += a2*bv.w;
            acc[3][0] += a3*bv.x; acc[3][1] += a3*bv.y; acc[3][2] += a3*bv.z; acc[3][3] += a3*bv.w;
        }
        __syncthreads();
    }

    if (lane == 0) {
        #pragma unroll
        for (int i = 0; i < 8; ++i) larr[w*8 + i] = lreg[i];
    }
    __syncthreads();
    #pragma unroll
    for (int i = 0; i < 4; ++i) {
        const float inv = 1.0f / larr[ty*4 + i];
        const int gq = qt*64 + ty*4 + i;
        float4 o;
        o.x = acc[i][0]*inv; o.y = acc[i][1]*inv;
        o.z = acc[i][2]*inv; o.w = acc[i][3]*inv;
        *(float4*)(Y + ((size_t)b * T_ + gq) * C_DIM + h*64 + tx*4) = o;
    }
}

// ---------------------------------------------------------------------------
extern "C" void kernel_launch(void* const* d_in, const int* in_sizes, int n_in,
                              void* d_out, int out_size)
{
    const float* x      = (const float*)d_in[0];
    const float* w_attn = (const float*)d_in[1];
    const float* b_attn = (const float*)d_in[2];
    const float* w_proj = (const float*)d_in[3];
    const float* b_proj = (const float*)d_in[4];
    float* out = (float*)d_out;

    float* yptr = nullptr;
    cudaGetSymbolAddress((void**)&yptr, g_y);

    cudaFuncSetAttribute(gemm_mma_kernel<1>,
                         cudaFuncAttributeMaxDynamicSharedMemorySize, GEMM_SMEM);
    cudaFuncSetAttribute(gemm_mma_kernel<0>,
                         cudaFuncAttributeMaxDynamicSharedMemorySize, GEMM_SMEM);
    cudaFuncSetAttribute(attn_kernel,
                         cudaFuncAttributeMaxDynamicSharedMemorySize, ATTN_SMEM);

    // 1) QKV projection (tf32 mma), epilogue scatters to head-major Q/K/V
    dim3 g1(QKV_N / 128, M_ROWS / 128);   // 24 x 64
    gemm_mma_kernel<1><<<g1, 256, GEMM_SMEM>>>(x, w_attn, b_attn, nullptr, QKV_N, C_DIM);

    // 2) Causal flash attention (fp32) -> g_y [B,T,C]
    dim3 g2(T_ / 64, B_ * H_);            // 32 x 64
    attn_kernel<<<g2, 256, ATTN_SMEM>>>(yptr);

    // 3) Output projection (tf32 mma) -> d_out
    dim3 g3(C_DIM / 128, M_ROWS / 128);   // 8 x 64
    gemm_mma_kernel<0><<<g3, 256, GEMM_SMEM>>>(yptr, w_proj, b_proj, out, C_DIM, C_DIM);
}

// round 4
// speedup vs baseline: 2.6739x; 1.7498x over previous
#include <cuda_runtime.h>
#include <cstdint>

// Problem constants
#define B_    4
#define T_    2048
#define C_DIM 1024
#define H_    16
#define D_    64
#define M_ROWS (B_*T_)      // 8192
#define QKV_N  (3*C_DIM)    // 3072
#define NEG_BIG (-3.0e38f)

// Scratch (device globals)
__device__ float g_q[8388608];   // [B,H,T,D]
__device__ float g_k[8388608];
__device__ float g_v[8388608];
__device__ float g_y[8388608];   // [B,T,C]

// ---------------------------------------------------------------------------
// Common helpers
// ---------------------------------------------------------------------------
__device__ __forceinline__ uint32_t cvta_smem(const void* p) {
    uint32_t a;
    asm("{ .reg .u64 t; cvta.to.shared.u64 t, %1; cvt.u32.u64 %0, t; }"
        : "=r"(a) : "l"(p));
    return a;
}
__device__ __forceinline__ void cp_async16(uint32_t dst, const void* src) {
    asm volatile("cp.async.cg.shared.global [%0], [%1], 16;" :: "r"(dst), "l"(src));
}
__device__ __forceinline__ void cp_commit() { asm volatile("cp.async.commit_group;"); }
__device__ __forceinline__ void cp_wait1()  { asm volatile("cp.async.wait_group 1;"); }
__device__ __forceinline__ void cp_wait0()  { asm volatile("cp.async.wait_group 0;"); }

// tf32 RNE rounding: destination of cvt.*.tf32 must be a .b32 register.
__device__ __forceinline__ uint32_t tf32_rne(float x) {
    uint32_t y;
    asm("cvt.rna.tf32.f32 %0, %1;" : "=r"(y) : "f"(x));
    return y;
}
__device__ __forceinline__ void mma_tf32(float* d, const uint32_t* a, const uint32_t* b) {
    asm volatile(
        "mma.sync.aligned.m16n8k8.row.col.f32.tf32.tf32.f32 "
        "{%0,%1,%2,%3}, {%4,%5,%6,%7}, {%8,%9}, {%0,%1,%2,%3};"
        : "+f"(d[0]), "+f"(d[1]), "+f"(d[2]), "+f"(d[3])
        : "r"(a[0]), "r"(a[1]), "r"(a[2]), "r"(a[3]), "r"(b[0]), "r"(b[1]));
}

// ---------------------------------------------------------------------------
// tf32 mma.sync GEMM (unchanged from round 3): out = A*W^T + bias
// ---------------------------------------------------------------------------
#define GPAD 36
#define GSM_BUF (128*GPAD)
#define GEMM_SMEM (4*GSM_BUF*(int)sizeof(float))

template<int MODE>
__global__ void __launch_bounds__(256) gemm_mma_kernel(
    const float* __restrict__ A, const float* __restrict__ W,
    const float* __restrict__ bias, float* __restrict__ out,
    int N, int K)
{
    extern __shared__ float sm[];
    const int tid  = threadIdx.x;
    const int lane = tid & 31;
    const int wid  = tid >> 5;
    const int wm   = wid & 1;
    const int wn   = wid >> 1;
    const int qr   = lane >> 2;
    const int qc   = lane & 3;

    const int rowBase = blockIdx.y * 128;
    const int colBase = blockIdx.x * 128;

    const int lrow = tid >> 1;
    const int lk0  = (tid & 1) << 4;
    const float* Asrc = A + (size_t)(rowBase + lrow) * K + lk0;
    const float* Wsrc = W + (size_t)(colBase + lrow) * K + lk0;
    const uint32_t smem_base = cvta_smem(sm);
    const uint32_t dstA = smem_base + (lrow * GPAD + lk0) * 4;
    const uint32_t dstB = dstA + GSM_BUF * 4;

    float acc[4][4][4];
    #pragma unroll
    for (int i = 0; i < 4; ++i)
        #pragma unroll
        for (int j = 0; j < 4; ++j)
            #pragma unroll
            for (int r = 0; r < 4; ++r) acc[i][j][r] = 0.f;

    const int nk = K >> 5;

    #pragma unroll
    for (int j = 0; j < 4; ++j) {
        cp_async16(dstA + j * 16, Asrc + j * 4);
        cp_async16(dstB + j * 16, Wsrc + j * 4);
    }
    cp_commit();

    for (int kt = 0; kt < nk; ++kt) {
        if (kt + 1 < nk) {
            const uint32_t stoff = ((kt + 1) & 1) ? (uint32_t)(2 * GSM_BUF * 4) : 0u;
            const float* An = Asrc + (size_t)(kt + 1) * 32;
            const float* Wn = Wsrc + (size_t)(kt + 1) * 32;
            #pragma unroll
            for (int j = 0; j < 4; ++j) {
                cp_async16(dstA + stoff + j * 16, An + j * 4);
                cp_async16(dstB + stoff + j * 16, Wn + j * 4);
            }
            cp_commit();
            cp_wait1();
        } else {
            cp_wait0();
        }
        __syncthreads();

        const float* As = sm + ((kt & 1) ? 2 * GSM_BUF : 0);
        const float* Bs = As + GSM_BUF;

        #pragma unroll
        for (int ks = 0; ks < 4; ++ks) {
            const int kk = ks * 8 + qc;
            uint32_t af[4][4], bf[4][2];
            #pragma unroll
            for (int mt = 0; mt < 4; ++mt) {
                const int r = wm * 64 + mt * 16 + qr;
                af[mt][0] = tf32_rne(As[r * GPAD + kk]);
                af[mt][1] = tf32_rne(As[(r + 8) * GPAD + kk]);
                af[mt][2] = tf32_rne(As[r * GPAD + kk + 4]);
                af[mt][3] = tf32_rne(As[(r + 8) * GPAD + kk + 4]);
            }
            #pragma unroll
            for (int nt = 0; nt < 4; ++nt) {
                const int c = wn * 32 + nt * 8 + qr;
                bf[nt][0] = tf32_rne(Bs[c * GPAD + kk]);
                bf[nt][1] = tf32_rne(Bs[c * GPAD + kk + 4]);
            }
            #pragma unroll
            for (int mt = 0; mt < 4; ++mt)
                #pragma unroll
                for (int nt = 0; nt < 4; ++nt)
                    mma_tf32(acc[mt][nt], af[mt], bf[nt]);
        }
        __syncthreads();
    }

    #pragma unroll
    for (int nt = 0; nt < 4; ++nt) {
        const int n0 = colBase + wn * 32 + nt * 8 + qc * 2;
        const float b0 = bias[n0], b1 = bias[n0 + 1];
        #pragma unroll
        for (int mt = 0; mt < 4; ++mt) {
            const int m0 = rowBase + wm * 64 + mt * 16 + qr;
            float2 v0 = make_float2(acc[mt][nt][0] + b0, acc[mt][nt][1] + b1);
            float2 v1 = make_float2(acc[mt][nt][2] + b0, acc[mt][nt][3] + b1);
            if (MODE == 0) {
                *(float2*)(out + (size_t)m0 * N + n0)       = v0;
                *(float2*)(out + (size_t)(m0 + 8) * N + n0) = v1;
            } else {
                const int sector = n0 >> 10;
                const int c  = n0 & 1023;
                const int hh = c >> 6, dd = c & 63;
                float* dst = (sector == 0) ? g_q : (sector == 1) ? g_k : g_v;
                const int bb0 = m0 >> 11, tt0 = m0 & 2047;
                *(float2*)(dst + ((((size_t)bb0 * H_ + hh) * T_) + tt0) * D_ + dd) = v0;
                const int m1 = m0 + 8;
                const int bb1 = m1 >> 11, tt1 = m1 & 2047;
                *(float2*)(dst + ((((size_t)bb1 * H_ + hh) * T_) + tt1) * D_ + dd) = v1;
            }
        }
    }
}

// ---------------------------------------------------------------------------
// Tensor-core flash attention (tf32 mma).
// CTA = (b, h, 128-query tile), 8 warps, warp owns rows [w*16, w*16+16).
// K tiles of 64 keys. Smem: Qs[128][QP], Ks[64][QP], Vs[64][VP], Ps[128][QP],
// all values stored tf32-pre-rounded (bits in float slots).
// S-phase:  A = Qs rows (row-major), B = Ks[key][d] via col-fragment.
// PV-phase: A = Ps rows,             B = Vs[key][d] via col-fragment.
// QP=68: frag addr mod 32 = 4*qr+qc (bijective). VP=72: 8*qc+qr (bijective).
// ---------------------------------------------------------------------------
#define QP 68
#define VP 72
#define ATTN_SMEM ((128*QP + 64*QP + 64*VP + 128*QP) * (int)sizeof(float))  // 105472

__global__ void __launch_bounds__(256) attn_mma_kernel(float* __restrict__ Y)
{
    extern __shared__ float sm[];
    float* Qs = sm;                    // [128][QP]
    float* Ks = Qs + 128*QP;           // [64][QP]
    float* Vs = Ks + 64*QP;            // [64][VP]
    float* Ps = Vs + 64*VP;            // [128][QP]

    const int qt  = gridDim.x - 1 - blockIdx.x;   // big tiles first
    const int bh  = blockIdx.y;
    const int b   = bh >> 4, h = bh & 15;
    const int tid = threadIdx.x;
    const int lane = tid & 31;
    const int w    = tid >> 5;
    const int qr   = lane >> 2;
    const int qc   = lane & 3;

    const float* Qg = g_q + ((size_t)bh * T_ + qt * 128) * D_;
    const float* Kg = g_k + (size_t)bh * T_ * D_;
    const float* Vg = g_v + (size_t)bh * T_ * D_;

    // Load Q tile, fold scale, round to tf32
    #pragma unroll
    for (int t = 0; t < 8; ++t) {
        const int slot = tid + t * 256;          // 0..2047
        const int r  = slot >> 4;
        const int d0 = (slot & 15) << 2;
        float4 v = *(const float4*)(Qg + r * 64 + d0);
        uint4 u;
        u.x = tf32_rne(v.x * 0.125f);
        u.y = tf32_rne(v.y * 0.125f);
        u.z = tf32_rne(v.z * 0.125f);
        u.w = tf32_rne(v.w * 0.125f);
        *(uint4*)(Qs + r * QP + d0) = u;
    }

    float m0 = NEG_BIG, m1 = NEG_BIG, l0 = 0.f, l1 = 0.f;
    float oacc[8][4];
    #pragma unroll
    for (int nt = 0; nt < 8; ++nt)
        #pragma unroll
        for (int r = 0; r < 4; ++r) oacc[nt][r] = 0.f;

    const int row0 = w * 16 + qr;        // local q row (and row0+8)
    const int jmax = 2 * qt + 1;

    for (int j = 0; j <= jmax; ++j) {
        __syncthreads();   // previous tile's Ks/Vs reads done (also orders Qs on j=0)

        // Load K and V tiles (tf32-rounded, V kept untransposed [key][d])
        {
            const float* Kgt = Kg + j * 64 * 64;
            const float* Vgt = Vg + j * 64 * 64;
            #pragma unroll
            for (int t = 0; t < 4; ++t) {
                const int slot = tid + t * 256;  // 0..1023
                const int r  = slot >> 4;
                const int d0 = (slot & 15) << 2;
                float4 kv = *(const float4*)(Kgt + r * 64 + d0);
                uint4 ku;
                ku.x = tf32_rne(kv.x); ku.y = tf32_rne(kv.y);
                ku.z = tf32_rne(kv.z); ku.w = tf32_rne(kv.w);
                *(uint4*)(Ks + r * QP + d0) = ku;
                float4 vv = *(const float4*)(Vgt + r * 64 + d0);
                uint4 vu;
                vu.x = tf32_rne(vv.x); vu.y = tf32_rne(vv.y);
                vu.z = tf32_rne(vv.z); vu.w = tf32_rne(vv.w);
                *(uint4*)(Vs + r * VP + d0) = vu;
            }
        }
        __syncthreads();

        // Per-warp active n-tile count (causal pruning)
        int ntmax = 8;
        if (j == 2 * qt) {
            ntmax = 2 * w + 2; if (ntmax > 8) ntmax = 8;
        } else if (j == 2 * qt + 1) {
            ntmax = 2 * w - 6; if (ntmax < 0) ntmax = 0;
        }

        if (ntmax > 0) {
            // ---- S = Q K^T ----
            float sacc[8][4];
            #pragma unroll
            for (int nt = 0; nt < 8; ++nt)
                #pragma unroll
                for (int r = 0; r < 4; ++r) sacc[nt][r] = 0.f;

            #pragma unroll
            for (int kc = 0; kc < 8; ++kc) {
                uint32_t a[4];
                const uint32_t* qb = (const uint32_t*)(Qs + (w*16 + qr) * QP + kc*8 + qc);
                a[0] = qb[0];
                a[1] = qb[8 * QP];
                a[2] = qb[4];
                a[3] = qb[8 * QP + 4];
                #pragma unroll
                for (int nt = 0; nt < 8; ++nt) {
                    if (nt < ntmax) {
                        uint32_t bf[2];
                        const uint32_t* kb = (const uint32_t*)(Ks + (nt*8 + qr) * QP + kc*8 + qc);
                        bf[0] = kb[0];
                        bf[1] = kb[4];
                        mma_tf32(sacc[nt], a, bf);
                    }
                }
            }

            // ---- Causal mask (diagonal tiles only) ----
            if (j >= 2 * qt) {
                const int rel = (j - 2 * qt) * 64;
                #pragma unroll
                for (int nt = 0; nt < 8; ++nt) {
                    if (nt < ntmax) {
                        const int col = rel + nt * 8 + qc * 2;
                        if (col     > row0)     sacc[nt][0] = NEG_BIG;
                        if (col + 1 > row0)     sacc[nt][1] = NEG_BIG;
                        if (col     > row0 + 8) sacc[nt][2] = NEG_BIG;
                        if (col + 1 > row0 + 8) sacc[nt][3] = NEG_BIG;
                    }
                }
            }

            // ---- Online softmax (register C-fragments; quad shfl reductions) ----
            float rmax0 = NEG_BIG, rmax1 = NEG_BIG;
            #pragma unroll
            for (int nt = 0; nt < 8; ++nt) {
                if (nt < ntmax) {
                    rmax0 = fmaxf(rmax0, fmaxf(sacc[nt][0], sacc[nt][1]));
                    rmax1 = fmaxf(rmax1, fmaxf(sacc[nt][2], sacc[nt][3]));
                }
            }
            rmax0 = fmaxf(rmax0, __shfl_xor_sync(0xffffffffu, rmax0, 1));
            rmax0 = fmaxf(rmax0, __shfl_xor_sync(0xffffffffu, rmax0, 2));
            rmax1 = fmaxf(rmax1, __shfl_xor_sync(0xffffffffu, rmax1, 1));
            rmax1 = fmaxf(rmax1, __shfl_xor_sync(0xffffffffu, rmax1, 2));

            const float mn0 = fmaxf(m0, rmax0);
            const float mn1 = fmaxf(m1, rmax1);
            const float al0 = __expf(m0 - mn0);
            const float al1 = __expf(m1 - mn1);

            float rs0 = 0.f, rs1 = 0.f;
            #pragma unroll
            for (int nt = 0; nt < 8; ++nt) {
                if (nt < ntmax) {
                    const float p00 = __expf(sacc[nt][0] - mn0);
                    const float p01 = __expf(sacc[nt][1] - mn0);
                    const float p10 = __expf(sacc[nt][2] - mn1);
                    const float p11 = __expf(sacc[nt][3] - mn1);
                    rs0 += p00 + p01;
                    rs1 += p10 + p11;
                    uint2 u0; u0.x = tf32_rne(p00); u0.y = tf32_rne(p01);
                    uint2 u1; u1.x = tf32_rne(p10); u1.y = tf32_rne(p11);
                    *(uint2*)(Ps + row0 * QP + nt*8 + qc*2)       = u0;
                    *(uint2*)(Ps + (row0 + 8) * QP + nt*8 + qc*2) = u1;
                }
            }
            rs0 += __shfl_xor_sync(0xffffffffu, rs0, 1);
            rs0 += __shfl_xor_sync(0xffffffffu, rs0, 2);
            rs1 += __shfl_xor_sync(0xffffffffu, rs1, 1);
            rs1 += __shfl_xor_sync(0xffffffffu, rs1, 2);

            l0 = l0 * al0 + rs0;
            l1 = l1 * al1 + rs1;
            m0 = mn0;
            m1 = mn1;

            #pragma unroll
            for (int nt = 0; nt < 8; ++nt) {
                oacc[nt][0] *= al0; oacc[nt][1] *= al0;
                oacc[nt][2] *= al1; oacc[nt][3] *= al1;
            }

            __syncwarp();   // Ps stores visible to the whole warp before PV loads

            // ---- O += P V ----
            #pragma unroll
            for (int kc = 0; kc < 8; ++kc) {
                if (kc < ntmax) {
                    uint32_t a[4];
                    const uint32_t* pb = (const uint32_t*)(Ps + (w*16 + qr) * QP + kc*8 + qc);
                    a[0] = pb[0];
                    a[1] = pb[8 * QP];
                    a[2] = pb[4];
                    a[3] = pb[8 * QP + 4];
                    #pragma unroll
                    for (int nt = 0; nt < 8; ++nt) {
                        uint32_t bf[2];
                        const uint32_t* vb = (const uint32_t*)(Vs + (kc*8 + qc) * VP + nt*8 + qr);
                        bf[0] = vb[0];
                        bf[1] = vb[4 * VP];
                        mma_tf32(oacc[nt], a, bf);
                    }
                }
            }
        }
    }

    // Epilogue: normalize, write to g_y [B,T,C] at head offset
    const float inv0 = 1.0f / l0;
    const float inv1 = 1.0f / l1;
    const int gq0 = qt * 128 + row0;
    float* y0 = Y + ((size_t)b * T_ + gq0) * C_DIM + h * 64 + qc * 2;
    float* y1 = y0 + 8 * C_DIM;
    #pragma unroll
    for (int nt = 0; nt < 8; ++nt) {
        float2 v0 = make_float2(oacc[nt][0] * inv0, oacc[nt][1] * inv0);
        float2 v1 = make_float2(oacc[nt][2] * inv1, oacc[nt][3] * inv1);
        *(float2*)(y0 + nt * 8) = v0;
        *(float2*)(y1 + nt * 8) = v1;
    }
}

// ---------------------------------------------------------------------------
extern "C" void kernel_launch(void* const* d_in, const int* in_sizes, int n_in,
                              void* d_out, int out_size)
{
    const float* x      = (const float*)d_in[0];
    const float* w_attn = (const float*)d_in[1];
    const float* b_attn = (const float*)d_in[2];
    const float* w_proj = (const float*)d_in[3];
    const float* b_proj = (const float*)d_in[4];
    float* out = (float*)d_out;

    float* yptr = nullptr;
    cudaGetSymbolAddress((void**)&yptr, g_y);

    cudaFuncSetAttribute(gemm_mma_kernel<1>,
                         cudaFuncAttributeMaxDynamicSharedMemorySize, GEMM_SMEM);
    cudaFuncSetAttribute(gemm_mma_kernel<0>,
                         cudaFuncAttributeMaxDynamicSharedMemorySize, GEMM_SMEM);
    cudaFuncSetAttribute(attn_mma_kernel,
                         cudaFuncAttributeMaxDynamicSharedMemorySize, ATTN_SMEM);

    // 1) QKV projection (tf32 mma), epilogue scatters to head-major Q/K/V
    dim3 g1(QKV_N / 128, M_ROWS / 128);   // 24 x 64
    gemm_mma_kernel<1><<<g1, 256, GEMM_SMEM>>>(x, w_attn, b_attn, nullptr, QKV_N, C_DIM);

    // 2) Causal flash attention (tf32 mma) -> g_y [B,T,C]
    dim3 g2(T_ / 128, B_ * H_);           // 16 x 64
    attn_mma_kernel<<<g2, 256, ATTN_SMEM>>>(yptr);

    // 3) Output projection (tf32 mma) -> d_out
    dim3 g3(C_DIM / 128, M_ROWS / 128);   // 8 x 64
    gemm_mma_kernel<0><<<g3, 256, GEMM_SMEM>>>(yptr, w_proj, b_proj, out, C_DIM, C_DIM);
}

// round 5
// speedup vs baseline: 2.7626x; 1.0332x over previous
#include <cuda_runtime.h>
#include <cstdint>

// Problem constants
#define B_    4
#define T_    2048
#define C_DIM 1024
#define H_    16
#define D_    64
#define M_ROWS (B_*T_)      // 8192
#define QKV_N  (3*C_DIM)    // 3072
#define NEG_BIG (-3.0e38f)

// Scratch (device globals)
__device__ float g_q[8388608];    // [B,H,T,D]  tf32-prerounded (Q also pre-scaled)
__device__ float g_k[8388608];    // tf32-prerounded
__device__ float g_v[8388608];    // tf32-prerounded
__device__ float g_y[8388608];    // [B,T,C]    tf32-prerounded
__device__ float g_xr[8388608];   // x rounded to tf32
__device__ float g_war[3145728];  // w_attn rounded
__device__ float g_wpr[1048576];  // w_proj rounded

// ---------------------------------------------------------------------------
// Common helpers
// ---------------------------------------------------------------------------
__device__ __forceinline__ uint32_t cvta_smem(const void* p) {
    uint32_t a;
    asm("{ .reg .u64 t; cvta.to.shared.u64 t, %1; cvt.u32.u64 %0, t; }"
        : "=r"(a) : "l"(p));
    return a;
}
__device__ __forceinline__ void cp_async16(uint32_t dst, const void* src) {
    asm volatile("cp.async.cg.shared.global [%0], [%1], 16;" :: "r"(dst), "l"(src));
}
__device__ __forceinline__ void cp_commit() { asm volatile("cp.async.commit_group;"); }
__device__ __forceinline__ void cp_wait1()  { asm volatile("cp.async.wait_group 1;"); }
__device__ __forceinline__ void cp_wait0()  { asm volatile("cp.async.wait_group 0;"); }

__device__ __forceinline__ uint32_t tf32_rne(float x) {
    uint32_t y;
    asm("cvt.rna.tf32.f32 %0, %1;" : "=r"(y) : "f"(x));
    return y;
}
__device__ __forceinline__ void mma_tf32(float* d, const uint32_t* a, const uint32_t* b) {
    asm volatile(
        "mma.sync.aligned.m16n8k8.row.col.f32.tf32.tf32.f32 "
        "{%0,%1,%2,%3}, {%4,%5,%6,%7}, {%8,%9}, {%0,%1,%2,%3};"
        : "+f"(d[0]), "+f"(d[1]), "+f"(d[2]), "+f"(d[3])
        : "r"(a[0]), "r"(a[1]), "r"(a[2]), "r"(a[3]), "r"(b[0]), "r"(b[1]));
}

// ---------------------------------------------------------------------------
// Pre-pass: round fp32 -> tf32 bit pattern (stored in float slots)
// ---------------------------------------------------------------------------
__global__ void __launch_bounds__(256) round_kernel(
    const float* __restrict__ in, float* __restrict__ out)
{
    const int i = (blockIdx.x * 256 + threadIdx.x) * 4;
    float4 v = *(const float4*)(in + i);
    uint4 u;
    u.x = tf32_rne(v.x); u.y = tf32_rne(v.y);
    u.z = tf32_rne(v.z); u.w = tf32_rne(v.w);
    *(uint4*)(out + i) = u;
}

// ---------------------------------------------------------------------------
// tf32 mma GEMM, inputs pre-rounded (NO cvt in mainloop):
// out[m,n] = sum_k A[m,k]*W[n,k] + bias[n]
// Block 128x128x32, 8 warps (2x4), warp tile 64x32, cp.async double buffer.
// MODE 0: fp32 store. MODE 1: tf32-rounded scatter into g_q/g_k/g_v
//         (Q sector pre-scaled by 1/8 before rounding).
// ---------------------------------------------------------------------------
#define GPAD 36
#define GSM_BUF (128*GPAD)
#define GEMM_SMEM (4*GSM_BUF*(int)sizeof(float))

template<int MODE>
__global__ void __launch_bounds__(256) gemm_mma_kernel(
    const float* __restrict__ A, const float* __restrict__ W,
    const float* __restrict__ bias, float* __restrict__ out,
    int N, int K)
{
    extern __shared__ float sm[];
    const int tid  = threadIdx.x;
    const int lane = tid & 31;
    const int wid  = tid >> 5;
    const int wm   = wid & 1;
    const int wn   = wid >> 1;
    const int qr   = lane >> 2;
    const int qc   = lane & 3;

    const int rowBase = blockIdx.y * 128;
    const int colBase = blockIdx.x * 128;

    const int lrow = tid >> 1;
    const int lk0  = (tid & 1) << 4;
    const float* Asrc = A + (size_t)(rowBase + lrow) * K + lk0;
    const float* Wsrc = W + (size_t)(colBase + lrow) * K + lk0;
    const uint32_t smem_base = cvta_smem(sm);
    const uint32_t dstA = smem_base + (lrow * GPAD + lk0) * 4;
    const uint32_t dstB = dstA + GSM_BUF * 4;

    float acc[4][4][4];
    #pragma unroll
    for (int i = 0; i < 4; ++i)
        #pragma unroll
        for (int j = 0; j < 4; ++j)
            #pragma unroll
            for (int r = 0; r < 4; ++r) acc[i][j][r] = 0.f;

    const int nk = K >> 5;

    #pragma unroll
    for (int j = 0; j < 4; ++j) {
        cp_async16(dstA + j * 16, Asrc + j * 4);
        cp_async16(dstB + j * 16, Wsrc + j * 4);
    }
    cp_commit();

    for (int kt = 0; kt < nk; ++kt) {
        if (kt + 1 < nk) {
            const uint32_t stoff = ((kt + 1) & 1) ? (uint32_t)(2 * GSM_BUF * 4) : 0u;
            const float* An = Asrc + (size_t)(kt + 1) * 32;
            const float* Wn = Wsrc + (size_t)(kt + 1) * 32;
            #pragma unroll
            for (int j = 0; j < 4; ++j) {
                cp_async16(dstA + stoff + j * 16, An + j * 4);
                cp_async16(dstB + stoff + j * 16, Wn + j * 4);
            }
            cp_commit();
            cp_wait1();
        } else {
            cp_wait0();
        }
        __syncthreads();

        const uint32_t* As = (const uint32_t*)(sm + ((kt & 1) ? 2 * GSM_BUF : 0));
        const uint32_t* Bs = As + GSM_BUF;

        #pragma unroll
        for (int ks = 0; ks < 4; ++ks) {
            const int kk = ks * 8 + qc;
            uint32_t af[4][4], bf[4][2];
            #pragma unroll
            for (int mt = 0; mt < 4; ++mt) {
                const int r = wm * 64 + mt * 16 + qr;
                af[mt][0] = As[r * GPAD + kk];
                af[mt][1] = As[(r + 8) * GPAD + kk];
                af[mt][2] = As[r * GPAD + kk + 4];
                af[mt][3] = As[(r + 8) * GPAD + kk + 4];
            }
            #pragma unroll
            for (int nt = 0; nt < 4; ++nt) {
                const int c = wn * 32 + nt * 8 + qr;
                bf[nt][0] = Bs[c * GPAD + kk];
                bf[nt][1] = Bs[c * GPAD + kk + 4];
            }
            #pragma unroll
            for (int mt = 0; mt < 4; ++mt)
                #pragma unroll
                for (int nt = 0; nt < 4; ++nt)
                    mma_tf32(acc[mt][nt], af[mt], bf[nt]);
        }
        __syncthreads();
    }

    #pragma unroll
    for (int nt = 0; nt < 4; ++nt) {
        const int n0 = colBase + wn * 32 + nt * 8 + qc * 2;
        const float b0 = bias[n0], b1 = bias[n0 + 1];
        #pragma unroll
        for (int mt = 0; mt < 4; ++mt) {
            const int m0 = rowBase + wm * 64 + mt * 16 + qr;
            float2 v0 = make_float2(acc[mt][nt][0] + b0, acc[mt][nt][1] + b1);
            float2 v1 = make_float2(acc[mt][nt][2] + b0, acc[mt][nt][3] + b1);
            if (MODE == 0) {
                *(float2*)(out + (size_t)m0 * N + n0)       = v0;
                *(float2*)(out + (size_t)(m0 + 8) * N + n0) = v1;
            } else {
                const int sector = n0 >> 10;          // 0=Q 1=K 2=V
                const int c  = n0 & 1023;
                const int hh = c >> 6, dd = c & 63;
                float* dst = (sector == 0) ? g_q : (sector == 1) ? g_k : g_v;
                const float qs = (sector == 0) ? 0.125f : 1.0f;  // fold softmax scale into Q
                uint2 u0, u1;
                u0.x = tf32_rne(v0.x * qs); u0.y = tf32_rne(v0.y * qs);
                u1.x = tf32_rne(v1.x * qs); u1.y = tf32_rne(v1.y * qs);
                const int bb0 = m0 >> 11, tt0 = m0 & 2047;
                *(uint2*)(dst + ((((size_t)bb0 * H_ + hh) * T_) + tt0) * D_ + dd) = u0;
                const int m1 = m0 + 8;
                const int bb1 = m1 >> 11, tt1 = m1 & 2047;
                *(uint2*)(dst + ((((size_t)bb1 * H_ + hh) * T_) + tt1) * D_ + dd) = u1;
            }
        }
    }
}

// ---------------------------------------------------------------------------
// Tensor-core flash attention (tf32 mma). Q/K/V arrive tf32-prerounded
// (Q pre-scaled), so tile loads are raw copies / cp.async — no cvt.
// CTA = (b, h, 128-query tile), 8 warps, warp owns rows [w*16, w*16+16).
// ---------------------------------------------------------------------------
#define QP 68
#define VP 72
#define ATTN_SMEM ((128*QP + 64*QP + 64*VP + 128*QP) * (int)sizeof(float))  // 105472

__global__ void __launch_bounds__(256) attn_mma_kernel(float* __restrict__ Y)
{
    extern __shared__ float sm[];
    float* Qs = sm;                    // [128][QP]
    float* Ks = Qs + 128*QP;           // [64][QP]
    float* Vs = Ks + 64*QP;            // [64][VP]
    float* Ps = Vs + 64*VP;            // [128][QP]

    const int qt  = gridDim.x - 1 - blockIdx.x;   // big tiles first
    const int bh  = blockIdx.y;
    const int b   = bh >> 4, h = bh & 15;
    const int tid = threadIdx.x;
    const int lane = tid & 31;
    const int w    = tid >> 5;
    const int qr   = lane >> 2;
    const int qc   = lane & 3;

    const float* Qg = g_q + ((size_t)bh * T_ + qt * 128) * D_;
    const float* Kg = g_k + (size_t)bh * T_ * D_;
    const float* Vg = g_v + (size_t)bh * T_ * D_;

    const uint32_t smem_u = cvta_smem(sm);
    const uint32_t ks_u = smem_u + 128*QP*4;
    const uint32_t vs_u = ks_u + 64*QP*4;

    // Load Q tile (already scaled + tf32-rounded): raw copy
    #pragma unroll
    for (int t = 0; t < 8; ++t) {
        const int slot = tid + t * 256;          // 0..2047
        const int r  = slot >> 4;
        const int d0 = (slot & 15) << 2;
        *(float4*)(Qs + r * QP + d0) = *(const float4*)(Qg + r * 64 + d0);
    }

    float m0 = NEG_BIG, m1 = NEG_BIG, l0 = 0.f, l1 = 0.f;
    float oacc[8][4];
    #pragma unroll
    for (int nt = 0; nt < 8; ++nt)
        #pragma unroll
        for (int r = 0; r < 4; ++r) oacc[nt][r] = 0.f;

    const int row0 = w * 16 + qr;
    const int jmax = 2 * qt + 1;

    for (int j = 0; j <= jmax; ++j) {
        __syncthreads();   // previous tile's Ks/Vs reads done (also orders Qs on j=0)

        // K/V tile loads via cp.async (raw tf32 bits, no cvt)
        {
            const float* Kgt = Kg + j * 64 * 64;
            const float* Vgt = Vg + j * 64 * 64;
            #pragma unroll
            for (int t = 0; t < 4; ++t) {
                const int slot = tid + t * 256;  // 0..1023
                const int r  = slot >> 4;
                const int d0 = (slot & 15) << 2;
                cp_async16(ks_u + (r * QP + d0) * 4, Kgt + r * 64 + d0);
                cp_async16(vs_u + (r * VP + d0) * 4, Vgt + r * 64 + d0);
            }
            cp_commit();
            cp_wait0();
        }
        __syncthreads();

        // Per-warp active n-tile count (causal pruning)
        int ntmax = 8;
        if (j == 2 * qt) {
            ntmax = 2 * w + 2; if (ntmax > 8) ntmax = 8;
        } else if (j == 2 * qt + 1) {
            ntmax = 2 * w - 6; if (ntmax < 0) ntmax = 0;
        }

        if (ntmax > 0) {
            // ---- S = Q K^T ----
            float sacc[8][4];
            #pragma unroll
            for (int nt = 0; nt < 8; ++nt)
                #pragma unroll
                for (int r = 0; r < 4; ++r) sacc[nt][r] = 0.f;

            #pragma unroll
            for (int kc = 0; kc < 8; ++kc) {
                uint32_t a[4];
                const uint32_t* qb = (const uint32_t*)(Qs + (w*16 + qr) * QP + kc*8 + qc);
                a[0] = qb[0];
                a[1] = qb[8 * QP];
                a[2] = qb[4];
                a[3] = qb[8 * QP + 4];
                #pragma unroll
                for (int nt = 0; nt < 8; ++nt) {
                    if (nt < ntmax) {
                        uint32_t bf[2];
                        const uint32_t* kb = (const uint32_t*)(Ks + (nt*8 + qr) * QP + kc*8 + qc);
                        bf[0] = kb[0];
                        bf[1] = kb[4];
                        mma_tf32(sacc[nt], a, bf);
                    }
                }
            }

            // ---- Causal mask (diagonal tiles only) ----
            if (j >= 2 * qt) {
                const int rel = (j - 2 * qt) * 64;
                #pragma unroll
                for (int nt = 0; nt < 8; ++nt) {
                    if (nt < ntmax) {
                        const int col = rel + nt * 8 + qc * 2;
                        if (col     > row0)     sacc[nt][0] = NEG_BIG;
                        if (col + 1 > row0)     sacc[nt][1] = NEG_BIG;
                        if (col     > row0 + 8) sacc[nt][2] = NEG_BIG;
                        if (col + 1 > row0 + 8) sacc[nt][3] = NEG_BIG;
                    }
                }
            }

            // ---- Online softmax ----
            float rmax0 = NEG_BIG, rmax1 = NEG_BIG;
            #pragma unroll
            for (int nt = 0; nt < 8; ++nt) {
                if (nt < ntmax) {
                    rmax0 = fmaxf(rmax0, fmaxf(sacc[nt][0], sacc[nt][1]));
                    rmax1 = fmaxf(rmax1, fmaxf(sacc[nt][2], sacc[nt][3]));
                }
            }
            rmax0 = fmaxf(rmax0, __shfl_xor_sync(0xffffffffu, rmax0, 1));
            rmax0 = fmaxf(rmax0, __shfl_xor_sync(0xffffffffu, rmax0, 2));
            rmax1 = fmaxf(rmax1, __shfl_xor_sync(0xffffffffu, rmax1, 1));
            rmax1 = fmaxf(rmax1, __shfl_xor_sync(0xffffffffu, rmax1, 2));

            const float mn0 = fmaxf(m0, rmax0);
            const float mn1 = fmaxf(m1, rmax1);
            const float al0 = __expf(m0 - mn0);
            const float al1 = __expf(m1 - mn1);

            float rs0 = 0.f, rs1 = 0.f;
            #pragma unroll
            for (int nt = 0; nt < 8; ++nt) {
                if (nt < ntmax) {
                    const float p00 = __expf(sacc[nt][0] - mn0);
                    const float p01 = __expf(sacc[nt][1] - mn0);
                    const float p10 = __expf(sacc[nt][2] - mn1);
                    const float p11 = __expf(sacc[nt][3] - mn1);
                    rs0 += p00 + p01;
                    rs1 += p10 + p11;
                    uint2 u0; u0.x = tf32_rne(p00); u0.y = tf32_rne(p01);
                    uint2 u1; u1.x = tf32_rne(p10); u1.y = tf32_rne(p11);
                    *(uint2*)(Ps + row0 * QP + nt*8 + qc*2)       = u0;
                    *(uint2*)(Ps + (row0 + 8) * QP + nt*8 + qc*2) = u1;
                }
            }
            rs0 += __shfl_xor_sync(0xffffffffu, rs0, 1);
            rs0 += __shfl_xor_sync(0xffffffffu, rs0, 2);
            rs1 += __shfl_xor_sync(0xffffffffu, rs1, 1);
            rs1 += __shfl_xor_sync(0xffffffffu, rs1, 2);

            l0 = l0 * al0 + rs0;
            l1 = l1 * al1 + rs1;
            m0 = mn0;
            m1 = mn1;

            #pragma unroll
            for (int nt = 0; nt < 8; ++nt) {
                oacc[nt][0] *= al0; oacc[nt][1] *= al0;
                oacc[nt][2] *= al1; oacc[nt][3] *= al1;
            }

            __syncwarp();   // Ps stores visible warp-wide before PV loads

            // ---- O += P V ----
            #pragma unroll
            for (int kc = 0; kc < 8; ++kc) {
                if (kc < ntmax) {
                    uint32_t a[4];
                    const uint32_t* pb = (const uint32_t*)(Ps + (w*16 + qr) * QP + kc*8 + qc);
                    a[0] = pb[0];
                    a[1] = pb[8 * QP];
                    a[2] = pb[4];
                    a[3] = pb[8 * QP + 4];
                    #pragma unroll
                    for (int nt = 0; nt < 8; ++nt) {
                        uint32_t bf[2];
                        const uint32_t* vb = (const uint32_t*)(Vs + (kc*8 + qc) * VP + nt*8 + qr);
                        bf[0] = vb[0];
                        bf[1] = vb[4 * VP];
                        mma_tf32(oacc[nt], a, bf);
                    }
                }
            }
        }
    }

    // Epilogue: normalize, round to tf32 (gemm2 consumes raw bits), store
    const float inv0 = 1.0f / l0;
    const float inv1 = 1.0f / l1;
    const int gq0 = qt * 128 + row0;
    float* y0 = Y + ((size_t)b * T_ + gq0) * C_DIM + h * 64 + qc * 2;
    float* y1 = y0 + 8 * C_DIM;
    #pragma unroll
    for (int nt = 0; nt < 8; ++nt) {
        uint2 u0, u1;
        u0.x = tf32_rne(oacc[nt][0] * inv0);
        u0.y = tf32_rne(oacc[nt][1] * inv0);
        u1.x = tf32_rne(oacc[nt][2] * inv1);
        u1.y = tf32_rne(oacc[nt][3] * inv1);
        *(uint2*)(y0 + nt * 8) = u0;
        *(uint2*)(y1 + nt * 8) = u1;
    }
}

// ---------------------------------------------------------------------------
extern "C" void kernel_launch(void* const* d_in, const int* in_sizes, int n_in,
                              void* d_out, int out_size)
{
    const float* x      = (const float*)d_in[0];
    const float* w_attn = (const float*)d_in[1];
    const float* b_attn = (const float*)d_in[2];
    const float* w_proj = (const float*)d_in[3];
    const float* b_proj = (const float*)d_in[4];
    float* out = (float*)d_out;

    float *yptr = nullptr, *xr = nullptr, *war = nullptr, *wpr = nullptr;
    cudaGetSymbolAddress((void**)&yptr, g_y);
    cudaGetSymbolAddress((void**)&xr,   g_xr);
    cudaGetSymbolAddress((void**)&war,  g_war);
    cudaGetSymbolAddress((void**)&wpr,  g_wpr);

    cudaFuncSetAttribute(gemm_mma_kernel<1>,
                         cudaFuncAttributeMaxDynamicSharedMemorySize, GEMM_SMEM);
    cudaFuncSetAttribute(gemm_mma_kernel<0>,
                         cudaFuncAttributeMaxDynamicSharedMemorySize, GEMM_SMEM);
    cudaFuncSetAttribute(attn_mma_kernel,
                         cudaFuncAttributeMaxDynamicSharedMemorySize, ATTN_SMEM);

    // 0) Pre-round inputs to tf32 (hoists all cvt out of GEMM mainloops)
    round_kernel<<<(M_ROWS * C_DIM) / 1024, 256>>>(x, xr);
    round_kernel<<<(QKV_N * C_DIM) / 1024, 256>>>(w_attn, war);
    round_kernel<<<(C_DIM * C_DIM) / 1024, 256>>>(w_proj, wpr);

    // 1) QKV projection; epilogue rounds + scatters Q(scaled)/K/V
    dim3 g1(QKV_N / 128, M_ROWS / 128);   // 24 x 64
    gemm_mma_kernel<1><<<g1, 256, GEMM_SMEM>>>(xr, war, b_attn, nullptr, QKV_N, C_DIM);

    // 2) Causal flash attention (tf32 mma) -> g_y (tf32-rounded)
    dim3 g2(T_ / 128, B_ * H_);           // 16 x 64
    attn_mma_kernel<<<g2, 256, ATTN_SMEM>>>(yptr);

    // 3) Output projection -> d_out (fp32)
    dim3 g3(C_DIM / 128, M_ROWS / 128);   // 8 x 64
    gemm_mma_kernel<0><<<g3, 256, GEMM_SMEM>>>(yptr, wpr, b_proj, out, C_DIM, C_DIM);
}